// round 7
// baseline (speedup 1.0000x reference)
#include <cuda_runtime.h>
#include <cuda_bf16.h>
#include <cstdint>
#include <math.h>

#define BATCH 96
#define NQ 196
#define NR 77
#define DIM 512
#define KC 32                  // k elements per chunk (bf16: 64 B data per row)
#define NCHUNK (DIM / KC)      // 16
#define NPAD 80
#define ROWB 80                // row stride bytes (64 data + 16 pad)

// ---------------- device scratch ----------------
__device__ __nv_bfloat16 g_ib0[BATCH * NQ * DIM];
__device__ __nv_bfloat16 g_ib1[BATCH * NQ * DIM];
__device__ __nv_bfloat16 g_tb0[BATCH * NR * DIM];
__device__ __nv_bfloat16 g_tb1[BATCH * NR * DIM];
__device__ float g_rowsum_part[2 * BATCH * BATCH];          // [mtile][b][c]
__device__ float g_colmax_part[2 * BATCH * BATCH * NPAD];   // [mtile][c][b][r]
__device__ float g_i2t[BATCH * BATCH];
__device__ float g_t2i[BATCH * BATCH];
__device__ float g_contrib[2 * BATCH];

// ---------------- PTX helpers (base sm_103 ISA only) ----------------
__device__ __forceinline__ uint32_t smem_u32(const void* p) {
    uint32_t a;
    asm("{ .reg .u64 t; cvta.to.shared.u64 t, %1; cvt.u32.u64 %0, t; }" : "=r"(a) : "l"(p));
    return a;
}
#define CP_ASYNC16(sa, gp, sz) \
    asm volatile("cp.async.cg.shared.global [%0], [%1], 16, %2;" \
        :: "r"(sa), "l"(gp), "r"(sz) : "memory")
#define CP_COMMIT()  asm volatile("cp.async.commit_group;" ::: "memory")
#define CP_WAIT2()   asm volatile("cp.async.wait_group 2;" ::: "memory")

#define LDSM_X4(r0, r1, r2, r3, a) \
    asm volatile("ldmatrix.sync.aligned.m8n8.x4.shared.b16 {%0,%1,%2,%3}, [%4];" \
        : "=r"(r0), "=r"(r1), "=r"(r2), "=r"(r3) : "r"(a))
#define LDSM_X2(r0, r1, a) \
    asm volatile("ldmatrix.sync.aligned.m8n8.x2.shared.b16 {%0,%1}, [%2];" \
        : "=r"(r0), "=r"(r1) : "r"(a))

#define MMA_BF16(d, a0, a1, a2, a3, b0, b1) \
    asm volatile("mma.sync.aligned.m16n8k16.row.col.f32.bf16.bf16.f32 " \
        "{%0,%1,%2,%3}, {%4,%5,%6,%7}, {%8,%9}, {%0,%1,%2,%3};" \
        : "+f"((d)[0]), "+f"((d)[1]), "+f"((d)[2]), "+f"((d)[3]) \
        : "r"(a0), "r"(a1), "r"(a2), "r"(a3), "r"(b0), "r"(b1))

// ===== precompute: split fp32 into bf16 hi (b0) and residual (b1) =====
__global__ void fg_split_kernel(const float* __restrict__ src,
                                __nv_bfloat16* __restrict__ b0,
                                __nv_bfloat16* __restrict__ b1, int n)
{
    int i = blockIdx.x * blockDim.x + threadIdx.x;
    if (i < n) {
        float x = src[i];
        __nv_bfloat16 h = __float2bfloat16(x);
        b0[i] = h;
        b1[i] = __float2bfloat16(x - __bfloat162float(h));
    }
}

// ======================================================================
// bf16x2 (3-pass) MMA kernel. CTA tile: MROWS x 80 (ONE text).
// MWARPS M-warps x 2 N-warps; NT = MWARPS*64 threads. MW = MROWS/MWARPS.
// Each N-warp covers 40 cols of the text: 2x LDSM.x4 frags + 1x LDSM.x2.
// grid = (96 images, 96 texts). mt = m-tile id, valid = valid image rows.
// ======================================================================
template <int MROWS, int MWARPS>
__global__ __launch_bounds__(MWARPS * 64, 2) void fg_mma_kernel(int mt, int valid)
{
    constexpr int NT   = MWARPS * 64;
    constexpr int MW   = MROWS / MWARPS;   // rows per M-warp
    constexpr int MF   = MW / 16;          // 16-row frags per warp
    constexpr int A_SZ = MROWS * ROWB;     // per part
    constexpr int B_SZ = NPAD * ROWB;      // 6400 per part
    constexpr int STAGE = 2 * A_SZ + 2 * B_SZ;

    extern __shared__ char smem_raw[];
    __shared__ float rowpart[MWARPS * 2][MW];
    __shared__ float scmax[MWARPS][NPAD];
    __shared__ float swsum[NT / 32];

    const uint32_t raw_u  = smem_u32(smem_raw);
    const uint32_t tile_u = (raw_u + 1023u) & ~1023u;

    const int tid = threadIdx.x;
    const int wid = tid >> 5;
    const int lid = tid & 31;
    const int wm = wid >> 1;          // 0..MWARPS-1
    const int wn = wid & 1;           // col half (0: cols 0-39, 1: 40-79)
    const int g  = lid >> 3;
    const int r  = lid & 7;

    const int bimg = blockIdx.x;
    const int c    = blockIdx.y;

    const size_t Abase = ((size_t)bimg * NQ + mt * 128) * DIM;
    const size_t Tbase = (size_t)c * NR * DIM;

    float acc[MF][5][4];
#pragma unroll
    for (int mf = 0; mf < MF; ++mf)
#pragma unroll
        for (int fn = 0; fn < 5; ++fn)
#pragma unroll
            for (int cc = 0; cc < 4; ++cc) acc[mf][fn][cc] = 0.0f;

    // ---------------- staging (16B = 8 bf16 per cp.async) ----------------
    auto stage = [&](int ci, int buf) {
        const int k0 = ci * KC;
        const uint32_t base = tile_u + buf * STAGE;
        // A: MROWS rows x 4 16B-slots x {b0,b1}
#pragma unroll
        for (int i = 0; i < (MROWS * 8) / NT; ++i) {
            int idx = tid + i * NT;
            int arr = (idx >= MROWS * 4) ? 1 : 0;
            int rem = idx - arr * MROWS * 4;
            int row = rem >> 2, u = rem & 3;
            int crow = row < valid ? row : 0;
            const __nv_bfloat16* sp = (arr ? g_ib1 : g_ib0) + Abase + (size_t)crow * DIM + k0 + u * 8;
            uint32_t sz = (row < valid) ? 16u : 0u;
            uint32_t sa = base + arr * A_SZ + row * ROWB + u * 16;
            CP_ASYNC16(sa, sp, sz);
        }
        // B: 80 rows x 4 slots x {b0,b1} = 640 ops
#pragma unroll
        for (int i = 0; i < (640 + NT - 1) / NT; ++i) {
            int idx = tid + i * NT;
            if (idx < 640) {
                int arr = (idx >= 320) ? 1 : 0;
                int rem = idx - arr * 320;
                int row = rem >> 2, u = rem & 3;
                int crr = row < NR ? row : 0;
                const __nv_bfloat16* sp = (arr ? g_tb1 : g_tb0) + Tbase + (size_t)crr * DIM + k0 + u * 8;
                uint32_t sz = (row < NR) ? 16u : 0u;
                uint32_t sa = base + 2 * A_SZ + arr * B_SZ + row * ROWB + u * 16;
                CP_ASYNC16(sa, sp, sz);
            }
        }
        CP_COMMIT();
    };

    stage(0, 0);
    stage(1, 1);
    stage(2, 2);

    // per-lane ldmatrix row offsets (validated lane maps)
    const uint32_t a_row  = (uint32_t)((wm * MW + (g & 1) * 8 + r) * ROWB);
    const uint32_t a_ub   = (uint32_t)(g >> 1);
    const uint32_t b_row  = (uint32_t)((wn * 40 + (g >> 1) * 8 + r) * ROWB);
    const uint32_t b_ub   = (uint32_t)(g & 1);
    const uint32_t b2_row = (uint32_t)((wn * 40 + 32 + r) * ROWB);   // x2: lanes 0-15 used
    const uint32_t b2_ub  = (uint32_t)((lid >> 3) & 1);

    // ---------------- main loop ----------------
    for (int ci = 0; ci < NCHUNK; ++ci) {
        const int buf = ci % 3;
        CP_WAIT2();
        __syncthreads();

        const uint32_t sA = tile_u + buf * STAGE;
        const uint32_t sB = sA + 2 * A_SZ;

#pragma unroll
        for (int ks = 0; ks < 2; ++ks) {
            uint32_t a0[MF][4], a1[MF][4];
            const uint32_t a_ch = (uint32_t)(ks * 32) + a_ub * 16;
#pragma unroll
            for (int mf = 0; mf < MF; ++mf) {
                uint32_t ad = sA + a_row + (uint32_t)(mf * 16 * ROWB) + a_ch;
                LDSM_X4(a0[mf][0], a0[mf][1], a0[mf][2], a0[mf][3], ad);
                LDSM_X4(a1[mf][0], a1[mf][1], a1[mf][2], a1[mf][3], ad + A_SZ);
            }
            const uint32_t b_ch = (uint32_t)(ks * 32) + b_ub * 16;
#pragma unroll
            for (int p = 0; p < 2; ++p) {
                uint32_t bh[4], bl[4];
                uint32_t bd = sB + b_row + (uint32_t)(p * 16 * ROWB) + b_ch;
                LDSM_X4(bh[0], bh[1], bh[2], bh[3], bd);
                LDSM_X4(bl[0], bl[1], bl[2], bl[3], bd + B_SZ);
#pragma unroll
                for (int mf = 0; mf < MF; ++mf) {
                    MMA_BF16(acc[mf][2 * p],     a0[mf][0], a0[mf][1], a0[mf][2], a0[mf][3], bh[0], bh[1]);
                    MMA_BF16(acc[mf][2 * p],     a0[mf][0], a0[mf][1], a0[mf][2], a0[mf][3], bl[0], bl[1]);
                    MMA_BF16(acc[mf][2 * p],     a1[mf][0], a1[mf][1], a1[mf][2], a1[mf][3], bh[0], bh[1]);
                    MMA_BF16(acc[mf][2 * p + 1], a0[mf][0], a0[mf][1], a0[mf][2], a0[mf][3], bh[2], bh[3]);
                    MMA_BF16(acc[mf][2 * p + 1], a0[mf][0], a0[mf][1], a0[mf][2], a0[mf][3], bl[2], bl[3]);
                    MMA_BF16(acc[mf][2 * p + 1], a1[mf][0], a1[mf][1], a1[mf][2], a1[mf][3], bh[2], bh[3]);
                }
            }
            {   // last 8 cols of this warp's 40-col half (x2 frag)
                uint32_t bh2[2], bl2[2];
                uint32_t bd2 = sB + b2_row + (uint32_t)(ks * 32) + b2_ub * 16;
                LDSM_X2(bh2[0], bh2[1], bd2);
                LDSM_X2(bl2[0], bl2[1], bd2 + B_SZ);
#pragma unroll
                for (int mf = 0; mf < MF; ++mf) {
                    MMA_BF16(acc[mf][4], a0[mf][0], a0[mf][1], a0[mf][2], a0[mf][3], bh2[0], bh2[1]);
                    MMA_BF16(acc[mf][4], a0[mf][0], a0[mf][1], a0[mf][2], a0[mf][3], bl2[0], bl2[1]);
                    MMA_BF16(acc[mf][4], a1[mf][0], a1[mf][1], a1[mf][2], a1[mf][3], bh2[0], bh2[1]);
                }
            }
        }

        __syncthreads();
        if (ci + 3 < NCHUNK) stage(ci + 3, buf);
        else                 CP_COMMIT();
    }

    // ---------------- epilogue ----------------
    // acc (mf, fn, cc): row_l = wm*MW + mf*16 + (cc>=2)*8 + lid/4
    //                   col   = wn*40 + fn*8 + 2*(lid&3) + (cc&1)
    const int q4 = lid >> 2;
    const int c0b = 2 * (lid & 3);

    // per-warp row maxes over its 40 cols -> rowpart[wid][row within MW]
#pragma unroll
    for (int mf = 0; mf < MF; ++mf) {
#pragma unroll
        for (int h = 0; h < 2; ++h) {
            float m = -INFINITY;
#pragma unroll
            for (int fn = 0; fn < 5; ++fn) {
                int col = wn * 40 + fn * 8 + c0b;
                if (col < NR)     m = fmaxf(m, acc[mf][fn][h * 2 + 0]);
                if (col + 1 < NR) m = fmaxf(m, acc[mf][fn][h * 2 + 1]);
            }
            m = fmaxf(m, __shfl_xor_sync(0xFFFFFFFFu, m, 1));
            m = fmaxf(m, __shfl_xor_sync(0xFFFFFFFFu, m, 2));
            if ((lid & 3) == 0) rowpart[wid][mf * 16 + h * 8 + q4] = m;
        }
    }

    // per-warp col maxes -> scmax[wm][col]  (wn halves write disjoint cols)
#pragma unroll
    for (int fn = 0; fn < 5; ++fn) {
#pragma unroll
        for (int cb = 0; cb < 2; ++cb) {
            float m = -INFINITY;
#pragma unroll
            for (int mf = 0; mf < MF; ++mf)
#pragma unroll
                for (int h = 0; h < 2; ++h) {
                    int row_l = wm * MW + mf * 16 + h * 8 + q4;
                    if (row_l < valid) m = fmaxf(m, acc[mf][fn][h * 2 + cb]);
                }
            m = fmaxf(m, __shfl_xor_sync(0xFFFFFFFFu, m, 4));
            m = fmaxf(m, __shfl_xor_sync(0xFFFFFFFFu, m, 8));
            m = fmaxf(m, __shfl_xor_sync(0xFFFFFFFFu, m, 16));
            if (lid < 4) scmax[wm][wn * 40 + fn * 8 + 2 * lid + cb] = m;
        }
    }
    __syncthreads();

    // rowsum: merge the two N-halves per row, sum valid rows
    float v = 0.0f;
    if (tid < MROWS && tid < valid) {
        int row = tid;
        int wmr = row / MW, rl = row - wmr * MW;
        v = fmaxf(rowpart[wmr * 2 + 0][rl], rowpart[wmr * 2 + 1][rl]);
    }
#pragma unroll
    for (int off = 16; off > 0; off >>= 1)
        v += __shfl_xor_sync(0xFFFFFFFFu, v, off);
    if (lid == 0) swsum[wid] = v;
    __syncthreads();
    if (tid == 0) {
        float s = 0.f;
#pragma unroll
        for (int w = 0; w < NT / 32; ++w) s += swsum[w];
        g_rowsum_part[((size_t)mt * BATCH + bimg) * BATCH + c] = s;
    }

    if (tid < NPAD) {
        float m = scmax[0][tid];
#pragma unroll
        for (int w = 1; w < MWARPS; ++w) m = fmaxf(m, scmax[w][tid]);
        g_colmax_part[(((size_t)mt * BATCH + c) * BATCH + bimg) * NPAD + tid] = m;
    }
}

// ===== combine partial tiles into logit matrices =====
__global__ void fg_combine_kernel()
{
    const int c = blockIdx.x;    // 96
    const int b = threadIdx.x;   // 96
    float rs = g_rowsum_part[((size_t)0 * BATCH + b) * BATCH + c] +
               g_rowsum_part[((size_t)1 * BATCH + b) * BATCH + c];
    g_i2t[b * BATCH + c] = rs * (1.0f / NQ);

    const float* p0 = &g_colmax_part[(((size_t)0 * BATCH + c) * BATCH + b) * NPAD];
    const float* p1 = &g_colmax_part[(((size_t)1 * BATCH + c) * BATCH + b) * NPAD];
    float s = 0.f;
#pragma unroll
    for (int rr = 0; rr < NR; ++rr) s += fmaxf(p0[rr], p1[rr]);
    g_t2i[c * BATCH + b] = s * (1.0f / NR);
}

// ===== per-row cross-entropy (one warp per row, 192 rows) =====
__global__ void fg_rowce_kernel()
{
    const int wid = threadIdx.x >> 5;
    const int lid = threadIdx.x & 31;
    const int row = blockIdx.x * 32 + wid;
    if (row >= 2 * BATCH) return;
    const int label = (row < BATCH) ? row : row - BATCH;
    const float* base = (row < BATCH) ? &g_i2t[row * BATCH] : &g_t2i[(row - BATCH) * BATCH];

    float v0 = base[lid], v1 = base[lid + 32], v2 = base[lid + 64];
    float m = fmaxf(v0, fmaxf(v1, v2));
#pragma unroll
    for (int off = 16; off > 0; off >>= 1)
        m = fmaxf(m, __shfl_xor_sync(0xFFFFFFFFu, m, off));
    float s = expf(v0 - m) + expf(v1 - m) + expf(v2 - m);
#pragma unroll
    for (int off = 16; off > 0; off >>= 1)
        s += __shfl_xor_sync(0xFFFFFFFFu, s, off);
    float lse = m + logf(s);
    int slot = label >> 5, src = label & 31;
    float mine = (slot == 0) ? v0 : ((slot == 1) ? v1 : v2);
    float dval = __shfl_sync(0xFFFFFFFFu, mine, src);
    if (lid == 0) g_contrib[row] = lse - dval;
}

__global__ void fg_final_kernel(float* __restrict__ out)
{
    __shared__ float sred[192];
    const int t = threadIdx.x;
    sred[t] = g_contrib[t];
    __syncthreads();
    if (t == 0) {
        float s = 0.f;
        for (int i = 0; i < 2 * BATCH; i++) s += sred[i];
        out[0] = s * (0.5f / BATCH);
    }
}

extern "C" void kernel_launch(void* const* d_in, const int* in_sizes, int n_in,
                              void* d_out, int out_size)
{
    const float* img;
    const float* txt;
    if (in_sizes[0] > in_sizes[1]) { img = (const float*)d_in[0]; txt = (const float*)d_in[1]; }
    else                           { img = (const float*)d_in[1]; txt = (const float*)d_in[0]; }
    float* out = (float*)d_out;

    constexpr int STAGE0 = 2 * (128 * ROWB) + 2 * (NPAD * ROWB);   // 33280
    constexpr int STAGE1 = 2 * (96 * ROWB)  + 2 * (NPAD * ROWB);   // 28160
    constexpr int SMEM0  = 3 * STAGE0 + 1024;   // 100864
    constexpr int SMEM1  = 3 * STAGE1 + 1024;   // 85504

    static int configured = 0;
    if (!configured) {
        cudaFuncSetAttribute(fg_mma_kernel<128, 4>, cudaFuncAttributeMaxDynamicSharedMemorySize, SMEM0);
        cudaFuncSetAttribute(fg_mma_kernel<96, 2>,  cudaFuncAttributeMaxDynamicSharedMemorySize, SMEM1);
        configured = 1;
    }

    // bf16 hi/lo split of both inputs
    {
        __nv_bfloat16 *ib0, *ib1, *tb0, *tb1;
        cudaGetSymbolAddress((void**)&ib0, g_ib0);
        cudaGetSymbolAddress((void**)&ib1, g_ib1);
        cudaGetSymbolAddress((void**)&tb0, g_tb0);
        cudaGetSymbolAddress((void**)&tb1, g_tb1);
        int ni = BATCH * NQ * DIM, nt = BATCH * NR * DIM;
        fg_split_kernel<<<(ni + 255) / 256, 256>>>(img, ib0, ib1, ni);
        fg_split_kernel<<<(nt + 255) / 256, 256>>>(txt, tb0, tb1, nt);
    }

    fg_mma_kernel<128, 4><<<dim3(BATCH, BATCH), 256, SMEM0>>>(0, 128);
    fg_mma_kernel<96, 2> <<<dim3(BATCH, BATCH), 128, SMEM1>>>(1, NQ - 128);
    fg_combine_kernel<<<BATCH, BATCH>>>();
    fg_rowce_kernel<<<6, 1024>>>();
    fg_final_kernel<<<1, 192>>>(out);
}

// round 8
// speedup vs baseline: 1.0241x; 1.0241x over previous
#include <cuda_runtime.h>
#include <cuda_bf16.h>
#include <cstdint>
#include <math.h>

#define BATCH 96
#define NQ 196
#define NR 77
#define DIM 512
#define KC 32                  // k elements per chunk (bf16: 64 B data per row)
#define NCHUNK (DIM / KC)      // 16
#define NPAD 80
#define ROWB 80                // row stride bytes (64 data + 16 pad)

// ---------------- device scratch ----------------
__device__ __nv_bfloat16 g_ib0[BATCH * NQ * DIM];
__device__ __nv_bfloat16 g_ib1[BATCH * NQ * DIM];
__device__ __nv_bfloat16 g_tb0[BATCH * NR * DIM];
__device__ __nv_bfloat16 g_tb1[BATCH * NR * DIM];
__device__ float g_rowsum_part[2 * BATCH * BATCH];          // [mtile][b][c]
__device__ float g_colmax_part[2 * BATCH * BATCH * NPAD];   // [mtile][c][b][r]
__device__ float g_i2t[BATCH * BATCH];
__device__ float g_t2i[BATCH * BATCH];
__device__ float g_contrib[2 * BATCH];

// ---------------- PTX helpers (base sm_103 ISA only) ----------------
__device__ __forceinline__ uint32_t smem_u32(const void* p) {
    uint32_t a;
    asm("{ .reg .u64 t; cvta.to.shared.u64 t, %1; cvt.u32.u64 %0, t; }" : "=r"(a) : "l"(p));
    return a;
}
#define CP_ASYNC16(sa, gp, sz) \
    asm volatile("cp.async.cg.shared.global [%0], [%1], 16, %2;" \
        :: "r"(sa), "l"(gp), "r"(sz) : "memory")
#define CP_COMMIT()  asm volatile("cp.async.commit_group;" ::: "memory")
#define CP_WAIT2()   asm volatile("cp.async.wait_group 2;" ::: "memory")

#define LDSM_X4(r0, r1, r2, r3, a) \
    asm volatile("ldmatrix.sync.aligned.m8n8.x4.shared.b16 {%0,%1,%2,%3}, [%4];" \
        : "=r"(r0), "=r"(r1), "=r"(r2), "=r"(r3) : "r"(a))
#define LDSM_X2(r0, r1, a) \
    asm volatile("ldmatrix.sync.aligned.m8n8.x2.shared.b16 {%0,%1}, [%2];" \
        : "=r"(r0), "=r"(r1) : "r"(a))

#define MMA_BF16(d, a0, a1, a2, a3, b0, b1) \
    asm volatile("mma.sync.aligned.m16n8k16.row.col.f32.bf16.bf16.f32 " \
        "{%0,%1,%2,%3}, {%4,%5,%6,%7}, {%8,%9}, {%0,%1,%2,%3};" \
        : "+f"((d)[0]), "+f"((d)[1]), "+f"((d)[2]), "+f"((d)[3]) \
        : "r"(a0), "r"(a1), "r"(a2), "r"(a3), "r"(b0), "r"(b1))

// ===== precompute: split fp32 into bf16 hi (b0) and residual (b1) =====
__global__ void fg_split_kernel(const float* __restrict__ src,
                                __nv_bfloat16* __restrict__ b0,
                                __nv_bfloat16* __restrict__ b1, int n)
{
    int i = blockIdx.x * blockDim.x + threadIdx.x;
    if (i < n) {
        float x = src[i];
        __nv_bfloat16 h = __float2bfloat16(x);
        b0[i] = h;
        b1[i] = __float2bfloat16(x - __bfloat162float(h));
    }
}

// ======================================================================
// bf16x2 (3-pass) MMA kernel. CTA tile: MROWS x 80 (ONE text).
// MWARPS M-warps x 2 N-warps; NT = MWARPS*64 threads. MW = MROWS/MWARPS.
// Pass-major MMA issue order breaks accumulator RAW chains.
// grid = (96 images, 96 texts). mt = m-tile id, valid = valid image rows.
// ======================================================================
template <int MROWS, int MWARPS>
__global__ __launch_bounds__(MWARPS * 64, 2) void fg_mma_kernel(int mt, int valid)
{
    constexpr int NT   = MWARPS * 64;
    constexpr int MW   = MROWS / MWARPS;   // rows per M-warp
    constexpr int MF   = MW / 16;          // 16-row frags per warp
    constexpr int A_SZ = MROWS * ROWB;     // per part
    constexpr int B_SZ = NPAD * ROWB;      // 6400 per part
    constexpr int STAGE = 2 * A_SZ + 2 * B_SZ;

    extern __shared__ char smem_raw[];
    __shared__ float rowpart[MWARPS * 2][MW];
    __shared__ float scmax[MWARPS][NPAD];
    __shared__ float swsum[NT / 32];

    const uint32_t raw_u  = smem_u32(smem_raw);
    const uint32_t tile_u = (raw_u + 1023u) & ~1023u;

    const int tid = threadIdx.x;
    const int wid = tid >> 5;
    const int lid = tid & 31;
    const int wm = wid >> 1;          // 0..MWARPS-1
    const int wn = wid & 1;           // col half (0: cols 0-39, 1: 40-79)
    const int g  = lid >> 3;
    const int r  = lid & 7;

    const int bimg = blockIdx.x;
    const int c    = blockIdx.y;

    const size_t Abase = ((size_t)bimg * NQ + mt * 128) * DIM;
    const size_t Tbase = (size_t)c * NR * DIM;

    float acc[MF][5][4];
#pragma unroll
    for (int mf = 0; mf < MF; ++mf)
#pragma unroll
        for (int fn = 0; fn < 5; ++fn)
#pragma unroll
            for (int cc = 0; cc < 4; ++cc) acc[mf][fn][cc] = 0.0f;

    // ---------------- staging (16B = 8 bf16 per cp.async) ----------------
    auto stage = [&](int ci, int buf) {
        const int k0 = ci * KC;
        const uint32_t base = tile_u + buf * STAGE;
        // A: MROWS rows x 4 16B-slots x {b0,b1}
#pragma unroll
        for (int i = 0; i < (MROWS * 8) / NT; ++i) {
            int idx = tid + i * NT;
            int arr = (idx >= MROWS * 4) ? 1 : 0;
            int rem = idx - arr * MROWS * 4;
            int row = rem >> 2, u = rem & 3;
            int crow = row < valid ? row : 0;
            const __nv_bfloat16* sp = (arr ? g_ib1 : g_ib0) + Abase + (size_t)crow * DIM + k0 + u * 8;
            uint32_t sz = (row < valid) ? 16u : 0u;
            uint32_t sa = base + arr * A_SZ + row * ROWB + u * 16;
            CP_ASYNC16(sa, sp, sz);
        }
        // B: 80 rows x 4 slots x {b0,b1} = 640 ops
#pragma unroll
        for (int i = 0; i < (640 + NT - 1) / NT; ++i) {
            int idx = tid + i * NT;
            if (idx < 640) {
                int arr = (idx >= 320) ? 1 : 0;
                int rem = idx - arr * 320;
                int row = rem >> 2, u = rem & 3;
                int crr = row < NR ? row : 0;
                const __nv_bfloat16* sp = (arr ? g_tb1 : g_tb0) + Tbase + (size_t)crr * DIM + k0 + u * 8;
                uint32_t sz = (row < NR) ? 16u : 0u;
                uint32_t sa = base + 2 * A_SZ + arr * B_SZ + row * ROWB + u * 16;
                CP_ASYNC16(sa, sp, sz);
            }
        }
        CP_COMMIT();
    };

    stage(0, 0);
    stage(1, 1);
    stage(2, 2);

    // per-lane ldmatrix row offsets (validated lane maps)
    const uint32_t a_row  = (uint32_t)((wm * MW + (g & 1) * 8 + r) * ROWB);
    const uint32_t a_ub   = (uint32_t)(g >> 1);
    const uint32_t b_row  = (uint32_t)((wn * 40 + (g >> 1) * 8 + r) * ROWB);
    const uint32_t b_ub   = (uint32_t)(g & 1);
    const uint32_t b2_row = (uint32_t)((wn * 40 + 32 + r) * ROWB);   // x2: lanes 0-15 used
    const uint32_t b2_ub  = (uint32_t)((lid >> 3) & 1);

    // ---------------- main loop ----------------
    for (int ci = 0; ci < NCHUNK; ++ci) {
        const int buf = ci % 3;
        CP_WAIT2();
        __syncthreads();

        const uint32_t sA = tile_u + buf * STAGE;
        const uint32_t sB = sA + 2 * A_SZ;

#pragma unroll
        for (int ks = 0; ks < 2; ++ks) {
            uint32_t a0[MF][4], a1[MF][4];
            const uint32_t a_ch = (uint32_t)(ks * 32) + a_ub * 16;
#pragma unroll
            for (int mf = 0; mf < MF; ++mf) {
                uint32_t ad = sA + a_row + (uint32_t)(mf * 16 * ROWB) + a_ch;
                LDSM_X4(a0[mf][0], a0[mf][1], a0[mf][2], a0[mf][3], ad);
                LDSM_X4(a1[mf][0], a1[mf][1], a1[mf][2], a1[mf][3], ad + A_SZ);
            }
            const uint32_t b_ch = (uint32_t)(ks * 32) + b_ub * 16;
#pragma unroll
            for (int p = 0; p < 2; ++p) {
                uint32_t bh[4], bl[4];
                uint32_t bd = sB + b_row + (uint32_t)(p * 16 * ROWB) + b_ch;
                LDSM_X4(bh[0], bh[1], bh[2], bh[3], bd);
                LDSM_X4(bl[0], bl[1], bl[2], bl[3], bd + B_SZ);
                // pass-major issue: consecutive MMAs hit different accumulators
#pragma unroll
                for (int mf = 0; mf < MF; ++mf)
                    MMA_BF16(acc[mf][2 * p],     a0[mf][0], a0[mf][1], a0[mf][2], a0[mf][3], bh[0], bh[1]);
#pragma unroll
                for (int mf = 0; mf < MF; ++mf)
                    MMA_BF16(acc[mf][2 * p + 1], a0[mf][0], a0[mf][1], a0[mf][2], a0[mf][3], bh[2], bh[3]);
#pragma unroll
                for (int mf = 0; mf < MF; ++mf)
                    MMA_BF16(acc[mf][2 * p],     a0[mf][0], a0[mf][1], a0[mf][2], a0[mf][3], bl[0], bl[1]);
#pragma unroll
                for (int mf = 0; mf < MF; ++mf)
                    MMA_BF16(acc[mf][2 * p + 1], a0[mf][0], a0[mf][1], a0[mf][2], a0[mf][3], bl[2], bl[3]);
#pragma unroll
                for (int mf = 0; mf < MF; ++mf)
                    MMA_BF16(acc[mf][2 * p],     a1[mf][0], a1[mf][1], a1[mf][2], a1[mf][3], bh[0], bh[1]);
#pragma unroll
                for (int mf = 0; mf < MF; ++mf)
                    MMA_BF16(acc[mf][2 * p + 1], a1[mf][0], a1[mf][1], a1[mf][2], a1[mf][3], bh[2], bh[3]);
            }
            {   // last 8 cols of this warp's 40-col half (x2 frag)
                uint32_t bh2[2], bl2[2];
                uint32_t bd2 = sB + b2_row + (uint32_t)(ks * 32) + b2_ub * 16;
                LDSM_X2(bh2[0], bh2[1], bd2);
                LDSM_X2(bl2[0], bl2[1], bd2 + B_SZ);
#pragma unroll
                for (int mf = 0; mf < MF; ++mf)
                    MMA_BF16(acc[mf][4], a0[mf][0], a0[mf][1], a0[mf][2], a0[mf][3], bh2[0], bh2[1]);
#pragma unroll
                for (int mf = 0; mf < MF; ++mf)
                    MMA_BF16(acc[mf][4], a0[mf][0], a0[mf][1], a0[mf][2], a0[mf][3], bl2[0], bl2[1]);
#pragma unroll
                for (int mf = 0; mf < MF; ++mf)
                    MMA_BF16(acc[mf][4], a1[mf][0], a1[mf][1], a1[mf][2], a1[mf][3], bh2[0], bh2[1]);
            }
        }

        __syncthreads();
        if (ci + 3 < NCHUNK) stage(ci + 3, buf);
        else                 CP_COMMIT();
    }

    // ---------------- epilogue ----------------
    // acc (mf, fn, cc): row_l = wm*MW + mf*16 + (cc>=2)*8 + lid/4
    //                   col   = wn*40 + fn*8 + 2*(lid&3) + (cc&1)
    const int q4 = lid >> 2;
    const int c0b = 2 * (lid & 3);

    // per-warp row maxes over its 40 cols -> rowpart[wid][row within MW]
#pragma unroll
    for (int mf = 0; mf < MF; ++mf) {
#pragma unroll
        for (int h = 0; h < 2; ++h) {
            float m = -INFINITY;
#pragma unroll
            for (int fn = 0; fn < 5; ++fn) {
                int col = wn * 40 + fn * 8 + c0b;
                if (col < NR)     m = fmaxf(m, acc[mf][fn][h * 2 + 0]);
                if (col + 1 < NR) m = fmaxf(m, acc[mf][fn][h * 2 + 1]);
            }
            m = fmaxf(m, __shfl_xor_sync(0xFFFFFFFFu, m, 1));
            m = fmaxf(m, __shfl_xor_sync(0xFFFFFFFFu, m, 2));
            if ((lid & 3) == 0) rowpart[wid][mf * 16 + h * 8 + q4] = m;
        }
    }

    // per-warp col maxes -> scmax[wm][col]  (wn halves write disjoint cols)
#pragma unroll
    for (int fn = 0; fn < 5; ++fn) {
#pragma unroll
        for (int cb = 0; cb < 2; ++cb) {
            float m = -INFINITY;
#pragma unroll
            for (int mf = 0; mf < MF; ++mf)
#pragma unroll
                for (int h = 0; h < 2; ++h) {
                    int row_l = wm * MW + mf * 16 + h * 8 + q4;
                    if (row_l < valid) m = fmaxf(m, acc[mf][fn][h * 2 + cb]);
                }
            m = fmaxf(m, __shfl_xor_sync(0xFFFFFFFFu, m, 4));
            m = fmaxf(m, __shfl_xor_sync(0xFFFFFFFFu, m, 8));
            m = fmaxf(m, __shfl_xor_sync(0xFFFFFFFFu, m, 16));
            if (lid < 4) scmax[wm][wn * 40 + fn * 8 + 2 * lid + cb] = m;
        }
    }
    __syncthreads();

    // rowsum: merge the two N-halves per row, sum valid rows
    float v = 0.0f;
    if (tid < MROWS && tid < valid) {
        int row = tid;
        int wmr = row / MW, rl = row - wmr * MW;
        v = fmaxf(rowpart[wmr * 2 + 0][rl], rowpart[wmr * 2 + 1][rl]);
    }
#pragma unroll
    for (int off = 16; off > 0; off >>= 1)
        v += __shfl_xor_sync(0xFFFFFFFFu, v, off);
    if (lid == 0) swsum[wid] = v;
    __syncthreads();
    if (tid == 0) {
        float s = 0.f;
#pragma unroll
        for (int w = 0; w < NT / 32; ++w) s += swsum[w];
        g_rowsum_part[((size_t)mt * BATCH + bimg) * BATCH + c] = s;
    }

    if (tid < NPAD) {
        float m = scmax[0][tid];
#pragma unroll
        for (int w = 1; w < MWARPS; ++w) m = fmaxf(m, scmax[w][tid]);
        g_colmax_part[(((size_t)mt * BATCH + c) * BATCH + bimg) * NPAD + tid] = m;
    }
}

// ===== combine partial tiles into logit matrices =====
__global__ void fg_combine_kernel()
{
    const int c = blockIdx.x;    // 96
    const int b = threadIdx.x;   // 96
    float rs = g_rowsum_part[((size_t)0 * BATCH + b) * BATCH + c] +
               g_rowsum_part[((size_t)1 * BATCH + b) * BATCH + c];
    g_i2t[b * BATCH + c] = rs * (1.0f / NQ);

    const float* p0 = &g_colmax_part[(((size_t)0 * BATCH + c) * BATCH + b) * NPAD];
    const float* p1 = &g_colmax_part[(((size_t)1 * BATCH + c) * BATCH + b) * NPAD];
    float s = 0.f;
#pragma unroll
    for (int rr = 0; rr < NR; ++rr) s += fmaxf(p0[rr], p1[rr]);
    g_t2i[c * BATCH + b] = s * (1.0f / NR);
}

// ===== per-row cross-entropy (one warp per row, 192 rows) =====
__global__ void fg_rowce_kernel()
{
    const int wid = threadIdx.x >> 5;
    const int lid = threadIdx.x & 31;
    const int row = blockIdx.x * 32 + wid;
    if (row >= 2 * BATCH) return;
    const int label = (row < BATCH) ? row : row - BATCH;
    const float* base = (row < BATCH) ? &g_i2t[row * BATCH] : &g_t2i[(row - BATCH) * BATCH];

    float v0 = base[lid], v1 = base[lid + 32], v2 = base[lid + 64];
    float m = fmaxf(v0, fmaxf(v1, v2));
#pragma unroll
    for (int off = 16; off > 0; off >>= 1)
        m = fmaxf(m, __shfl_xor_sync(0xFFFFFFFFu, m, off));
    float s = expf(v0 - m) + expf(v1 - m) + expf(v2 - m);
#pragma unroll
    for (int off = 16; off > 0; off >>= 1)
        s += __shfl_xor_sync(0xFFFFFFFFu, s, off);
    float lse = m + logf(s);
    int slot = label >> 5, src = label & 31;
    float mine = (slot == 0) ? v0 : ((slot == 1) ? v1 : v2);
    float dval = __shfl_sync(0xFFFFFFFFu, mine, src);
    if (lid == 0) g_contrib[row] = lse - dval;
}

__global__ void fg_final_kernel(float* __restrict__ out)
{
    __shared__ float sred[192];
    const int t = threadIdx.x;
    sred[t] = g_contrib[t];
    __syncthreads();
    if (t == 0) {
        float s = 0.f;
        for (int i = 0; i < 2 * BATCH; i++) s += sred[i];
        out[0] = s * (0.5f / BATCH);
    }
}

extern "C" void kernel_launch(void* const* d_in, const int* in_sizes, int n_in,
                              void* d_out, int out_size)
{
    const float* img;
    const float* txt;
    if (in_sizes[0] > in_sizes[1]) { img = (const float*)d_in[0]; txt = (const float*)d_in[1]; }
    else                           { img = (const float*)d_in[1]; txt = (const float*)d_in[0]; }
    float* out = (float*)d_out;

    constexpr int STAGE0 = 2 * (128 * ROWB) + 2 * (NPAD * ROWB);   // 33280
    constexpr int STAGE1 = 2 * (96 * ROWB)  + 2 * (NPAD * ROWB);   // 28160
    constexpr int SMEM0  = 3 * STAGE0 + 1024;   // 100864 -> 2 CTAs/SM
    constexpr int SMEM1  = 3 * STAGE1 + 1024;   // 85504  -> 2 CTAs/SM

    static int configured = 0;
    if (!configured) {
        cudaFuncSetAttribute(fg_mma_kernel<128, 2>, cudaFuncAttributeMaxDynamicSharedMemorySize, SMEM0);
        cudaFuncSetAttribute(fg_mma_kernel<96, 2>,  cudaFuncAttributeMaxDynamicSharedMemorySize, SMEM1);
        configured = 1;
    }

    // bf16 hi/lo split of both inputs
    {
        __nv_bfloat16 *ib0, *ib1, *tb0, *tb1;
        cudaGetSymbolAddress((void**)&ib0, g_ib0);
        cudaGetSymbolAddress((void**)&ib1, g_ib1);
        cudaGetSymbolAddress((void**)&tb0, g_tb0);
        cudaGetSymbolAddress((void**)&tb1, g_tb1);
        int ni = BATCH * NQ * DIM, nt = BATCH * NR * DIM;
        fg_split_kernel<<<(ni + 255) / 256, 256>>>(img, ib0, ib1, ni);
        fg_split_kernel<<<(nt + 255) / 256, 256>>>(txt, tb0, tb1, nt);
    }

    fg_mma_kernel<128, 2><<<dim3(BATCH, BATCH), 128, SMEM0>>>(0, 128);
    fg_mma_kernel<96, 2> <<<dim3(BATCH, BATCH), 128, SMEM1>>>(1, NQ - 128);
    fg_combine_kernel<<<BATCH, BATCH>>>();
    fg_rowce_kernel<<<6, 1024>>>();
    fg_final_kernel<<<1, 192>>>(out);
}

// round 9
// speedup vs baseline: 1.1451x; 1.1181x over previous
#include <cuda_runtime.h>
#include <cuda_bf16.h>
#include <cstdint>
#include <math.h>

#define BATCH 96
#define NQ 196
#define NR 77
#define DIM 512
#define KC 32                  // k elements per chunk
#define NCHUNK (DIM / KC)      // 16
#define NPAD 80
#define ROWB 80                // row stride bytes (64 data + 16 pad, conflict-free)
#define NTILES 3               // m-tiles: 96 + 96 + 16

// ---------------- device scratch ----------------
__device__ __nv_bfloat16 g_ib0[BATCH * NQ * DIM];
__device__ __nv_bfloat16 g_ib1[BATCH * NQ * DIM];
__device__ __nv_bfloat16 g_tb0[BATCH * NR * DIM];
__device__ __nv_bfloat16 g_tb1[BATCH * NR * DIM];
__device__ float g_rowsum_part[NTILES * BATCH * BATCH];          // [mt][b][c]
__device__ float g_colmax_part[NTILES * BATCH * BATCH * NPAD];   // [mt][c][b][r]
__device__ float g_i2t[BATCH * BATCH];
__device__ float g_t2i[BATCH * BATCH];
__device__ float g_contrib[2 * BATCH];

// ---------------- PTX helpers (base sm_103 ISA only) ----------------
__device__ __forceinline__ uint32_t smem_u32(const void* p) {
    uint32_t a;
    asm("{ .reg .u64 t; cvta.to.shared.u64 t, %1; cvt.u32.u64 %0, t; }" : "=r"(a) : "l"(p));
    return a;
}
#define CP_ASYNC16(sa, gp, sz) \
    asm volatile("cp.async.cg.shared.global [%0], [%1], 16, %2;" \
        :: "r"(sa), "l"(gp), "r"(sz) : "memory")
#define CP_COMMIT()  asm volatile("cp.async.commit_group;" ::: "memory")
#define CP_WAIT1()   asm volatile("cp.async.wait_group 1;" ::: "memory")

#define LDSM_X4(r0, r1, r2, r3, a) \
    asm volatile("ldmatrix.sync.aligned.m8n8.x4.shared.b16 {%0,%1,%2,%3}, [%4];" \
        : "=r"(r0), "=r"(r1), "=r"(r2), "=r"(r3) : "r"(a))

#define MMA_BF16(d, a0, a1, a2, a3, b0, b1) \
    asm volatile("mma.sync.aligned.m16n8k16.row.col.f32.bf16.bf16.f32 " \
        "{%0,%1,%2,%3}, {%4,%5,%6,%7}, {%8,%9}, {%0,%1,%2,%3};" \
        : "+f"((d)[0]), "+f"((d)[1]), "+f"((d)[2]), "+f"((d)[3]) \
        : "r"(a0), "r"(a1), "r"(a2), "r"(a3), "r"(b0), "r"(b1))

// ===== precompute: split fp32 into bf16 hi (b0) and residual (b1) =====
__global__ void fg_split_kernel(const float* __restrict__ src,
                                __nv_bfloat16* __restrict__ b0,
                                __nv_bfloat16* __restrict__ b1, int n)
{
    int i = blockIdx.x * blockDim.x + threadIdx.x;
    if (i < n) {
        float x = src[i];
        __nv_bfloat16 h = __float2bfloat16(x);
        b0[i] = h;
        b1[i] = __float2bfloat16(x - __bfloat162float(h));
    }
}

// ======================================================================
// bf16x2 (3-pass) MMA kernel. CTA tile: MROWS x 160 (TWO texts).
// Warps: MWARPS (M) x 2 (N); each N-warp owns ONE FULL text (80 cols).
// NT = MWARPS*64 threads. MW = MROWS/MWARPS rows per M-warp.
// 2-stage cp.async pipeline, 2 CTAs/SM.
// grid = (96 images, 48 text-pairs, z m-tiles). mt = mt_base + blockIdx.z.
// ======================================================================
template <int MROWS, int MWARPS>
__global__ __launch_bounds__(MWARPS * 64, 2) void fg_mma_kernel(int mt_base, int valid)
{
    constexpr int NT   = MWARPS * 64;
    constexpr int MW   = MROWS / MWARPS;
    constexpr int MF   = MW / 16;
    constexpr int A_SZ = MROWS * ROWB;       // per part
    constexpr int B_SZ = 2 * NPAD * ROWB;    // 12800 per part (two texts)
    constexpr int STAGE = 2 * A_SZ + 2 * B_SZ;

    extern __shared__ char smem_raw[];
    __shared__ float scmax[MWARPS][2][NPAD];
    __shared__ float swsum[NT / 32];

    const uint32_t raw_u  = smem_u32(smem_raw);
    const uint32_t tile_u = (raw_u + 1023u) & ~1023u;

    const int tid = threadIdx.x;
    const int wid = tid >> 5;
    const int lid = tid & 31;
    const int wn = wid & 1;           // text within pair
    const int wm = wid >> 1;          // 0..MWARPS-1
    const int g  = lid >> 3;
    const int r  = lid & 7;

    const int bimg = blockIdx.x;
    const int cg   = blockIdx.y;
    const int mt   = mt_base + blockIdx.z;

    const size_t Abase = ((size_t)bimg * NQ + mt * 96) * DIM;
    const size_t Tbase = (size_t)(cg * 2) * NR * DIM;

    float acc[MF][10][4];
#pragma unroll
    for (int mf = 0; mf < MF; ++mf)
#pragma unroll
        for (int fn = 0; fn < 10; ++fn)
#pragma unroll
            for (int cc = 0; cc < 4; ++cc) acc[mf][fn][cc] = 0.0f;

    // ---------------- staging ----------------
    auto stage = [&](int ci, int buf) {
        const int k0 = ci * KC;
        const uint32_t base = tile_u + buf * STAGE;
        // A: MROWS rows x 4 slots x {b0,b1}
#pragma unroll
        for (int i = 0; i < (MROWS * 8) / NT; ++i) {
            int idx = tid + i * NT;
            int arr = (idx >= MROWS * 4) ? 1 : 0;
            int rem = idx - arr * MROWS * 4;
            int row = rem >> 2, u = rem & 3;
            int crow = row < valid ? row : 0;
            const __nv_bfloat16* sp = (arr ? g_ib1 : g_ib0) + Abase + (size_t)crow * DIM + k0 + u * 8;
            uint32_t sz = (row < valid) ? 16u : 0u;
            uint32_t sa = base + arr * A_SZ + row * ROWB + u * 16;
            CP_ASYNC16(sa, sp, sz);
        }
        // B: 160 rows (2 texts x 80) x 4 slots x {b0,b1} = 1280 ops
#pragma unroll
        for (int i = 0; i < 1280 / NT; ++i) {
            int idx = tid + i * NT;
            int arr = (idx >= 640) ? 1 : 0;
            int rem = idx - arr * 640;
            int row = rem >> 2, u = rem & 3;
            int tg = row / NPAD, rr = row - tg * NPAD;
            int crr = rr < NR ? rr : 0;
            const __nv_bfloat16* sp = (arr ? g_tb1 : g_tb0) + Tbase + ((size_t)tg * NR + crr) * DIM + k0 + u * 8;
            uint32_t sz = (rr < NR) ? 16u : 0u;
            uint32_t sa = base + 2 * A_SZ + arr * B_SZ + row * ROWB + u * 16;
            CP_ASYNC16(sa, sp, sz);
        }
        CP_COMMIT();
    };

    stage(0, 0);
    stage(1, 1);

    // per-lane ldmatrix offsets (validated lane maps)
    const uint32_t a_row = (uint32_t)((wm * MW + (g & 1) * 8 + r) * ROWB);
    const uint32_t a_ub  = (uint32_t)(g >> 1);
    const uint32_t b_row = (uint32_t)((wn * NPAD + (g >> 1) * 8 + r) * ROWB);
    const uint32_t b_ub  = (uint32_t)(g & 1);

    // ---------------- main loop ----------------
    for (int ci = 0; ci < NCHUNK; ++ci) {
        const int buf = ci & 1;
        CP_WAIT1();
        __syncthreads();

        const uint32_t sA = tile_u + buf * STAGE;
        const uint32_t sB = sA + 2 * A_SZ;

#pragma unroll
        for (int ks = 0; ks < 2; ++ks) {
            uint32_t a0[MF][4], a1[MF][4];
            const uint32_t a_ch = (uint32_t)(ks * 32) + a_ub * 16;
#pragma unroll
            for (int mf = 0; mf < MF; ++mf) {
                uint32_t ad = sA + a_row + (uint32_t)(mf * 16 * ROWB) + a_ch;
                LDSM_X4(a0[mf][0], a0[mf][1], a0[mf][2], a0[mf][3], ad);
                LDSM_X4(a1[mf][0], a1[mf][1], a1[mf][2], a1[mf][3], ad + A_SZ);
            }
            const uint32_t b_ch = (uint32_t)(ks * 32) + b_ub * 16;
#pragma unroll
            for (int p = 0; p < 5; ++p) {
                uint32_t bh[4], bl[4];
                uint32_t bd = sB + b_row + (uint32_t)(p * 16 * ROWB) + b_ch;
                LDSM_X4(bh[0], bh[1], bh[2], bh[3], bd);
                LDSM_X4(bl[0], bl[1], bl[2], bl[3], bd + B_SZ);
#pragma unroll
                for (int mf = 0; mf < MF; ++mf)
                    MMA_BF16(acc[mf][2 * p],     a0[mf][0], a0[mf][1], a0[mf][2], a0[mf][3], bh[0], bh[1]);
#pragma unroll
                for (int mf = 0; mf < MF; ++mf)
                    MMA_BF16(acc[mf][2 * p + 1], a0[mf][0], a0[mf][1], a0[mf][2], a0[mf][3], bh[2], bh[3]);
#pragma unroll
                for (int mf = 0; mf < MF; ++mf)
                    MMA_BF16(acc[mf][2 * p],     a0[mf][0], a0[mf][1], a0[mf][2], a0[mf][3], bl[0], bl[1]);
#pragma unroll
                for (int mf = 0; mf < MF; ++mf)
                    MMA_BF16(acc[mf][2 * p + 1], a0[mf][0], a0[mf][1], a0[mf][2], a0[mf][3], bl[2], bl[3]);
#pragma unroll
                for (int mf = 0; mf < MF; ++mf)
                    MMA_BF16(acc[mf][2 * p],     a1[mf][0], a1[mf][1], a1[mf][2], a1[mf][3], bh[0], bh[1]);
#pragma unroll
                for (int mf = 0; mf < MF; ++mf)
                    MMA_BF16(acc[mf][2 * p + 1], a1[mf][0], a1[mf][1], a1[mf][2], a1[mf][3], bh[2], bh[3]);
            }
        }

        __syncthreads();
        if (ci + 2 < NCHUNK) stage(ci + 2, buf);
        else                 CP_COMMIT();   // keep group parity
    }

    // ---------------- epilogue ----------------
    // acc (mf, fn, cc): row_l = wm*MW + mf*16 + (cc>=2)*8 + lid/4
    //                   col   = fn*8 + 2*(lid&3) + (cc&1)   (within text wn)
    const int q4 = lid >> 2;
    const int c0b = 2 * (lid & 3);

    // this warp owns FULL cols of text wn: complete row-maxes
    float rsum = 0.0f;
#pragma unroll
    for (int mf = 0; mf < MF; ++mf) {
#pragma unroll
        for (int h = 0; h < 2; ++h) {
            float m = -INFINITY;
#pragma unroll
            for (int fn = 0; fn < 10; ++fn) {
                int col = fn * 8 + c0b;
                if (col < NR)     m = fmaxf(m, acc[mf][fn][h * 2 + 0]);
                if (col + 1 < NR) m = fmaxf(m, acc[mf][fn][h * 2 + 1]);
            }
            m = fmaxf(m, __shfl_xor_sync(0xFFFFFFFFu, m, 1));
            m = fmaxf(m, __shfl_xor_sync(0xFFFFFFFFu, m, 2));
            int row_l = wm * MW + mf * 16 + h * 8 + q4;
            if ((lid & 3) == 0 && row_l < valid) rsum += m;
        }
    }
#pragma unroll
    for (int off = 16; off > 0; off >>= 1)
        rsum += __shfl_xor_sync(0xFFFFFFFFu, rsum, off);
    if (lid == 0) swsum[wid] = rsum;

    // col maxes over this warp's rows
#pragma unroll
    for (int fn = 0; fn < 5; ++fn) {   // fn here iterates pairs via 2 cb each -> use 10 fn directly
    }
#pragma unroll
    for (int fn = 0; fn < 10; ++fn) {
#pragma unroll
        for (int cb = 0; cb < 2; ++cb) {
            float m = -INFINITY;
#pragma unroll
            for (int mf = 0; mf < MF; ++mf)
#pragma unroll
                for (int h = 0; h < 2; ++h) {
                    int row_l = wm * MW + mf * 16 + h * 8 + q4;
                    if (row_l < valid) m = fmaxf(m, acc[mf][fn][h * 2 + cb]);
                }
            m = fmaxf(m, __shfl_xor_sync(0xFFFFFFFFu, m, 4));
            m = fmaxf(m, __shfl_xor_sync(0xFFFFFFFFu, m, 8));
            m = fmaxf(m, __shfl_xor_sync(0xFFFFFFFFu, m, 16));
            if (lid < 4) scmax[wm][wn][fn * 8 + 2 * lid + cb] = m;
        }
    }
    __syncthreads();

    if (tid < 2) {
        float s = swsum[tid];
#pragma unroll
        for (int w = 1; w < MWARPS; ++w) s += swsum[w * 2 + tid];
        g_rowsum_part[((size_t)mt * BATCH + bimg) * BATCH + cg * 2 + tid] = s;
    }
    for (int idx = tid; idx < 2 * NPAD; idx += NT) {
        int wn2 = idx / NPAD, col = idx - wn2 * NPAD;
        float m = scmax[0][wn2][col];
#pragma unroll
        for (int w = 1; w < MWARPS; ++w) m = fmaxf(m, scmax[w][wn2][col]);
        int c = cg * 2 + wn2;
        g_colmax_part[(((size_t)mt * BATCH + c) * BATCH + bimg) * NPAD + col] = m;
    }
}

// ===== combine partial tiles into logit matrices =====
__global__ void fg_combine_kernel()
{
    const int c = blockIdx.x;    // 96
    const int b = threadIdx.x;   // 96
    float rs = 0.f;
#pragma unroll
    for (int t = 0; t < NTILES; ++t)
        rs += g_rowsum_part[((size_t)t * BATCH + b) * BATCH + c];
    g_i2t[b * BATCH + c] = rs * (1.0f / NQ);

    const float* p0 = &g_colmax_part[(((size_t)0 * BATCH + c) * BATCH + b) * NPAD];
    const float* p1 = &g_colmax_part[(((size_t)1 * BATCH + c) * BATCH + b) * NPAD];
    const float* p2 = &g_colmax_part[(((size_t)2 * BATCH + c) * BATCH + b) * NPAD];
    float s = 0.f;
#pragma unroll
    for (int rr = 0; rr < NR; ++rr) s += fmaxf(fmaxf(p0[rr], p1[rr]), p2[rr]);
    g_t2i[c * BATCH + b] = s * (1.0f / NR);
}

// ===== per-row cross-entropy (one warp per row, 192 rows) =====
__global__ void fg_rowce_kernel()
{
    const int wid = threadIdx.x >> 5;
    const int lid = threadIdx.x & 31;
    const int row = blockIdx.x * 32 + wid;
    if (row >= 2 * BATCH) return;
    const int label = (row < BATCH) ? row : row - BATCH;
    const float* base = (row < BATCH) ? &g_i2t[row * BATCH] : &g_t2i[(row - BATCH) * BATCH];

    float v0 = base[lid], v1 = base[lid + 32], v2 = base[lid + 64];
    float m = fmaxf(v0, fmaxf(v1, v2));
#pragma unroll
    for (int off = 16; off > 0; off >>= 1)
        m = fmaxf(m, __shfl_xor_sync(0xFFFFFFFFu, m, off));
    float s = expf(v0 - m) + expf(v1 - m) + expf(v2 - m);
#pragma unroll
    for (int off = 16; off > 0; off >>= 1)
        s += __shfl_xor_sync(0xFFFFFFFFu, s, off);
    float lse = m + logf(s);
    int slot = label >> 5, src = label & 31;
    float mine = (slot == 0) ? v0 : ((slot == 1) ? v1 : v2);
    float dval = __shfl_sync(0xFFFFFFFFu, mine, src);
    if (lid == 0) g_contrib[row] = lse - dval;
}

__global__ void fg_final_kernel(float* __restrict__ out)
{
    __shared__ float sred[192];
    const int t = threadIdx.x;
    sred[t] = g_contrib[t];
    __syncthreads();
    if (t == 0) {
        float s = 0.f;
        for (int i = 0; i < 2 * BATCH; i++) s += sred[i];
        out[0] = s * (0.5f / BATCH);
    }
}

extern "C" void kernel_launch(void* const* d_in, const int* in_sizes, int n_in,
                              void* d_out, int out_size)
{
    const float* img;
    const float* txt;
    if (in_sizes[0] > in_sizes[1]) { img = (const float*)d_in[0]; txt = (const float*)d_in[1]; }
    else                           { img = (const float*)d_in[1]; txt = (const float*)d_in[0]; }
    float* out = (float*)d_out;

    constexpr int STAGE_MAIN = 2 * (96 * ROWB) + 2 * (2 * NPAD * ROWB);   // 40960
    constexpr int STAGE_TAIL = 2 * (16 * ROWB) + 2 * (2 * NPAD * ROWB);   // 28160
    constexpr int SMEM_MAIN  = 2 * STAGE_MAIN + 1024;   // 82944 -> 2 CTAs/SM
    constexpr int SMEM_TAIL  = 2 * STAGE_TAIL + 1024;   // 57344

    static int configured = 0;
    if (!configured) {
        cudaFuncSetAttribute(fg_mma_kernel<96, 2>, cudaFuncAttributeMaxDynamicSharedMemorySize, SMEM_MAIN);
        cudaFuncSetAttribute(fg_mma_kernel<16, 1>, cudaFuncAttributeMaxDynamicSharedMemorySize, SMEM_TAIL);
        configured = 1;
    }

    // bf16 hi/lo split of both inputs
    {
        __nv_bfloat16 *ib0, *ib1, *tb0, *tb1;
        cudaGetSymbolAddress((void**)&ib0, g_ib0);
        cudaGetSymbolAddress((void**)&ib1, g_ib1);
        cudaGetSymbolAddress((void**)&tb0, g_tb0);
        cudaGetSymbolAddress((void**)&tb1, g_tb1);
        int ni = BATCH * NQ * DIM, nt = BATCH * NR * DIM;
        fg_split_kernel<<<(ni + 255) / 256, 256>>>(img, ib0, ib1, ni);
        fg_split_kernel<<<(nt + 255) / 256, 256>>>(txt, tb0, tb1, nt);
    }

    // m-tiles 0,1: rows 0-95, 96-191 (all valid). m-tile 2: rows 192-195 (4 valid of 16).
    fg_mma_kernel<96, 2><<<dim3(BATCH, BATCH / 2, 2), 128, SMEM_MAIN>>>(0, 96);
    fg_mma_kernel<16, 1><<<dim3(BATCH, BATCH / 2, 1), 64,  SMEM_TAIL>>>(2, 4);
    fg_combine_kernel<<<BATCH, BATCH>>>();
    fg_rowce_kernel<<<6, 1024>>>();
    fg_final_kernel<<<1, 192>>>(out);
}

// round 10
// speedup vs baseline: 1.3090x; 1.1432x over previous
#include <cuda_runtime.h>
#include <cuda_bf16.h>
#include <cstdint>
#include <math.h>

#define BATCH 96
#define NQ 196
#define NR 77
#define DIM 512
#define KC 32                  // k elements per chunk
#define NCHUNK (DIM / KC)      // 16
#define NPAD 80
#define ROWB 80                // row stride bytes (64 data + 16 pad, conflict-free)
#define NTILES 3               // m-tiles: 96 + 96 + (compacted 4-row tail)

// ---------------- device scratch ----------------
__device__ __nv_bfloat16 g_ib0[BATCH * NQ * DIM];
__device__ __nv_bfloat16 g_ib1[BATCH * NQ * DIM];
__device__ __nv_bfloat16 g_tb0[BATCH * NR * DIM];
__device__ __nv_bfloat16 g_tb1[BATCH * NR * DIM];
__device__ float g_rowsum_part[NTILES * BATCH * BATCH];          // [mt][b][c]
__device__ float g_colmax_part[NTILES * BATCH * BATCH * NPAD];   // [mt][c][b][r]
__device__ float g_i2t[BATCH * BATCH];
__device__ float g_t2i[BATCH * BATCH];
__device__ float g_contrib[2 * BATCH];

// ---------------- PTX helpers (base sm_103 ISA only) ----------------
__device__ __forceinline__ uint32_t smem_u32(const void* p) {
    uint32_t a;
    asm("{ .reg .u64 t; cvta.to.shared.u64 t, %1; cvt.u32.u64 %0, t; }" : "=r"(a) : "l"(p));
    return a;
}
#define CP_ASYNC16(sa, gp, sz) \
    asm volatile("cp.async.cg.shared.global [%0], [%1], 16, %2;" \
        :: "r"(sa), "l"(gp), "r"(sz) : "memory")
#define CP_COMMIT()  asm volatile("cp.async.commit_group;" ::: "memory")
#define CP_WAIT1()   asm volatile("cp.async.wait_group 1;" ::: "memory")

#define LDSM_X4(r0, r1, r2, r3, a) \
    asm volatile("ldmatrix.sync.aligned.m8n8.x4.shared.b16 {%0,%1,%2,%3}, [%4];" \
        : "=r"(r0), "=r"(r1), "=r"(r2), "=r"(r3) : "r"(a))

#define MMA_BF16(d, a0, a1, a2, a3, b0, b1) \
    asm volatile("mma.sync.aligned.m16n8k16.row.col.f32.bf16.bf16.f32 " \
        "{%0,%1,%2,%3}, {%4,%5,%6,%7}, {%8,%9}, {%0,%1,%2,%3};" \
        : "+f"((d)[0]), "+f"((d)[1]), "+f"((d)[2]), "+f"((d)[3]) \
        : "r"(a0), "r"(a1), "r"(a2), "r"(a3), "r"(b0), "r"(b1))

// ===== precompute: split fp32 into bf16 hi (b0) and residual (b1) =====
__global__ void fg_split_kernel(const float* __restrict__ src,
                                __nv_bfloat16* __restrict__ b0,
                                __nv_bfloat16* __restrict__ b1, int n)
{
    int i = blockIdx.x * blockDim.x + threadIdx.x;
    if (i < n) {
        float x = src[i];
        __nv_bfloat16 h = __float2bfloat16(x);
        b0[i] = h;
        b1[i] = __float2bfloat16(x - __bfloat162float(h));
    }
}

// ======================================================================
// bf16x2 (3-pass) MMA kernel. CTA tile: 96 x 160 (TWO texts).
// Warps: 2 (M) x 2 (N); each N-warp owns ONE FULL text (80 cols).
// TAIL=false: blockIdx.x = image, rows mt*96..mt*96+95 of that image.
// TAIL=true : blockIdx.x = tile (0..3); row r maps to image tile*24 + r/4,
//             token 192 + r%4  (compacted 4-row tails of 24 images).
//             Epilogue reduces per 4-row group (= per image).
// ======================================================================
template <bool TAIL>
__global__ __launch_bounds__(128, 2) void fg_mma_kernel(int mt_base)
{
    constexpr int MROWS = 96;
    constexpr int MWARPS = 2;
    constexpr int NT   = 128;
    constexpr int MW   = 48;
    constexpr int MF   = 3;
    constexpr int A_SZ = MROWS * ROWB;       // per part
    constexpr int B_SZ = 2 * NPAD * ROWB;    // 12800 per part (two texts)
    constexpr int STAGE = 2 * A_SZ + 2 * B_SZ;

    extern __shared__ char smem_raw[];
    __shared__ float scmax[MWARPS][2][NPAD];
    __shared__ float swsum[NT / 32];

    const uint32_t raw_u  = smem_u32(smem_raw);
    const uint32_t tile_u = (raw_u + 1023u) & ~1023u;

    const int tid = threadIdx.x;
    const int wid = tid >> 5;
    const int lid = tid & 31;
    const int wn = wid & 1;           // text within pair
    const int wm = wid >> 1;          // 0..1
    const int g  = lid >> 3;
    const int r  = lid & 7;

    const int bx   = blockIdx.x;      // image (main) or tile (tail)
    const int cg   = blockIdx.y;
    const int mt   = mt_base + blockIdx.z;

    const size_t Abase = TAIL ? 0 : ((size_t)bx * NQ + mt * 96) * DIM;
    const size_t Tbase = (size_t)(cg * 2) * NR * DIM;

    float acc[MF][10][4];
#pragma unroll
    for (int mf = 0; mf < MF; ++mf)
#pragma unroll
        for (int fn = 0; fn < 10; ++fn)
#pragma unroll
            for (int cc = 0; cc < 4; ++cc) acc[mf][fn][cc] = 0.0f;

    // ---------------- staging ----------------
    auto stage = [&](int ci, int buf) {
        const int k0 = ci * KC;
        const uint32_t base = tile_u + buf * STAGE;
        // A: 96 rows x 4 slots x {b0,b1} = 768 ops
#pragma unroll
        for (int i = 0; i < (MROWS * 8) / NT; ++i) {
            int idx = tid + i * NT;
            int arr = (idx >= MROWS * 4) ? 1 : 0;
            int rem = idx - arr * MROWS * 4;
            int row = rem >> 2, u = rem & 3;
            size_t off;
            if (TAIL) {
                int img = bx * 24 + (row >> 2);
                int q   = 192 + (row & 3);
                off = ((size_t)img * NQ + q) * DIM + k0 + u * 8;
            } else {
                off = Abase + (size_t)row * DIM + k0 + u * 8;
            }
            const __nv_bfloat16* sp = (arr ? g_ib1 : g_ib0) + off;
            uint32_t sa = base + arr * A_SZ + row * ROWB + u * 16;
            CP_ASYNC16(sa, sp, 16u);
        }
        // B: 160 rows (2 texts x 80) x 4 slots x {b0,b1} = 1280 ops
#pragma unroll
        for (int i = 0; i < 1280 / NT; ++i) {
            int idx = tid + i * NT;
            int arr = (idx >= 640) ? 1 : 0;
            int rem = idx - arr * 640;
            int row = rem >> 2, u = rem & 3;
            int tg = row / NPAD, rr = row - tg * NPAD;
            int crr = rr < NR ? rr : 0;
            const __nv_bfloat16* sp = (arr ? g_tb1 : g_tb0) + Tbase + ((size_t)tg * NR + crr) * DIM + k0 + u * 8;
            uint32_t sz = (rr < NR) ? 16u : 0u;
            uint32_t sa = base + 2 * A_SZ + arr * B_SZ + row * ROWB + u * 16;
            CP_ASYNC16(sa, sp, sz);
        }
        CP_COMMIT();
    };

    stage(0, 0);
    stage(1, 1);

    // per-lane ldmatrix offsets (validated lane maps)
    const uint32_t a_row = (uint32_t)((wm * MW + (g & 1) * 8 + r) * ROWB);
    const uint32_t a_ub  = (uint32_t)(g >> 1);
    const uint32_t b_row = (uint32_t)((wn * NPAD + (g >> 1) * 8 + r) * ROWB);
    const uint32_t b_ub  = (uint32_t)(g & 1);

    // ---------------- main loop ----------------
    for (int ci = 0; ci < NCHUNK; ++ci) {
        const int buf = ci & 1;
        CP_WAIT1();
        __syncthreads();

        const uint32_t sA = tile_u + buf * STAGE;
        const uint32_t sB = sA + 2 * A_SZ;

#pragma unroll
        for (int ks = 0; ks < 2; ++ks) {
            uint32_t a0[MF][4], a1[MF][4];
            const uint32_t a_ch = (uint32_t)(ks * 32) + a_ub * 16;
#pragma unroll
            for (int mf = 0; mf < MF; ++mf) {
                uint32_t ad = sA + a_row + (uint32_t)(mf * 16 * ROWB) + a_ch;
                LDSM_X4(a0[mf][0], a0[mf][1], a0[mf][2], a0[mf][3], ad);
                LDSM_X4(a1[mf][0], a1[mf][1], a1[mf][2], a1[mf][3], ad + A_SZ);
            }
            const uint32_t b_ch = (uint32_t)(ks * 32) + b_ub * 16;
#pragma unroll
            for (int p = 0; p < 5; ++p) {
                uint32_t bh[4], bl[4];
                uint32_t bd = sB + b_row + (uint32_t)(p * 16 * ROWB) + b_ch;
                LDSM_X4(bh[0], bh[1], bh[2], bh[3], bd);
                LDSM_X4(bl[0], bl[1], bl[2], bl[3], bd + B_SZ);
#pragma unroll
                for (int mf = 0; mf < MF; ++mf)
                    MMA_BF16(acc[mf][2 * p],     a0[mf][0], a0[mf][1], a0[mf][2], a0[mf][3], bh[0], bh[1]);
#pragma unroll
                for (int mf = 0; mf < MF; ++mf)
                    MMA_BF16(acc[mf][2 * p + 1], a0[mf][0], a0[mf][1], a0[mf][2], a0[mf][3], bh[2], bh[3]);
#pragma unroll
                for (int mf = 0; mf < MF; ++mf)
                    MMA_BF16(acc[mf][2 * p],     a0[mf][0], a0[mf][1], a0[mf][2], a0[mf][3], bl[0], bl[1]);
#pragma unroll
                for (int mf = 0; mf < MF; ++mf)
                    MMA_BF16(acc[mf][2 * p + 1], a0[mf][0], a0[mf][1], a0[mf][2], a0[mf][3], bl[2], bl[3]);
#pragma unroll
                for (int mf = 0; mf < MF; ++mf)
                    MMA_BF16(acc[mf][2 * p],     a1[mf][0], a1[mf][1], a1[mf][2], a1[mf][3], bh[0], bh[1]);
#pragma unroll
                for (int mf = 0; mf < MF; ++mf)
                    MMA_BF16(acc[mf][2 * p + 1], a1[mf][0], a1[mf][1], a1[mf][2], a1[mf][3], bh[2], bh[3]);
            }
        }

        __syncthreads();
        if (ci + 2 < NCHUNK) stage(ci + 2, buf);
        else                 CP_COMMIT();   // keep group parity
    }

    // ---------------- epilogue ----------------
    // acc (mf, fn, cc): row_l = wm*48 + mf*16 + (cc>=2)*8 + lid/4
    //                   col   = fn*8 + 2*(lid&3) + (cc&1)   (within text wn)
    const int c0b = 2 * (lid & 3);
    const int cdx = cg * 2 + wn;      // text index

    if (!TAIL) {
        const int q4 = lid >> 2;
        float rsum = 0.0f;
#pragma unroll
        for (int mf = 0; mf < MF; ++mf) {
#pragma unroll
            for (int h = 0; h < 2; ++h) {
                float m = -INFINITY;
#pragma unroll
                for (int fn = 0; fn < 10; ++fn) {
                    int col = fn * 8 + c0b;
                    if (col < NR)     m = fmaxf(m, acc[mf][fn][h * 2 + 0]);
                    if (col + 1 < NR) m = fmaxf(m, acc[mf][fn][h * 2 + 1]);
                }
                m = fmaxf(m, __shfl_xor_sync(0xFFFFFFFFu, m, 1));
                m = fmaxf(m, __shfl_xor_sync(0xFFFFFFFFu, m, 2));
                if ((lid & 3) == 0) rsum += m;
            }
        }
#pragma unroll
        for (int off = 16; off > 0; off >>= 1)
            rsum += __shfl_xor_sync(0xFFFFFFFFu, rsum, off);
        if (lid == 0) swsum[wid] = rsum;

#pragma unroll
        for (int fn = 0; fn < 10; ++fn) {
#pragma unroll
            for (int cb = 0; cb < 2; ++cb) {
                float m = -INFINITY;
#pragma unroll
                for (int mf = 0; mf < MF; ++mf)
#pragma unroll
                    for (int h = 0; h < 2; ++h)
                        m = fmaxf(m, acc[mf][fn][h * 2 + cb]);
                m = fmaxf(m, __shfl_xor_sync(0xFFFFFFFFu, m, 4));
                m = fmaxf(m, __shfl_xor_sync(0xFFFFFFFFu, m, 8));
                m = fmaxf(m, __shfl_xor_sync(0xFFFFFFFFu, m, 16));
                if (lid < 4) scmax[wm][wn][fn * 8 + 2 * lid + cb] = m;
            }
        }
        __syncthreads();

        if (tid < 2) {
            float s = swsum[tid];
#pragma unroll
            for (int w = 1; w < MWARPS; ++w) s += swsum[w * 2 + tid];
            g_rowsum_part[((size_t)mt * BATCH + bx) * BATCH + cg * 2 + tid] = s;
        }
        for (int idx = tid; idx < 2 * NPAD; idx += NT) {
            int wn2 = idx / NPAD, col = idx - wn2 * NPAD;
            float m = scmax[0][wn2][col];
#pragma unroll
            for (int w = 1; w < MWARPS; ++w) m = fmaxf(m, scmax[w][wn2][col]);
            int c = cg * 2 + wn2;
            g_colmax_part[(((size_t)mt * BATCH + c) * BATCH + bx) * NPAD + col] = m;
        }
    } else {
        // -------- tail epilogue: per-4-row-group (= per image) reductions --------
        // group (within warp) = mf*4 + h*2 + (q4>>2);  image = bx*24 + wm*12 + group
#pragma unroll
        for (int mf = 0; mf < MF; ++mf) {
#pragma unroll
            for (int h = 0; h < 2; ++h) {
                float m = -INFINITY;
#pragma unroll
                for (int fn = 0; fn < 10; ++fn) {
                    int col = fn * 8 + c0b;
                    if (col < NR)     m = fmaxf(m, acc[mf][fn][h * 2 + 0]);
                    if (col + 1 < NR) m = fmaxf(m, acc[mf][fn][h * 2 + 1]);
                }
                // row max across the 4 col-lanes of the quad
                m = fmaxf(m, __shfl_xor_sync(0xFFFFFFFFu, m, 1));
                m = fmaxf(m, __shfl_xor_sync(0xFFFFFFFFu, m, 2));
                // sum of the 4 row-maxes within the 4-row group (q4 bits 0,1)
                m += __shfl_xor_sync(0xFFFFFFFFu, m, 4);
                m += __shfl_xor_sync(0xFFFFFFFFu, m, 8);
                if ((lid & 15) == 0) {
                    int group = mf * 4 + h * 2 + (lid >> 4);
                    int img = bx * 24 + wm * 12 + group;
                    g_rowsum_part[((size_t)mt * BATCH + img) * BATCH + cdx] = m;
                }
            }
        }
        // col max per 4-row group
#pragma unroll
        for (int mf = 0; mf < MF; ++mf) {
#pragma unroll
            for (int h = 0; h < 2; ++h) {
#pragma unroll
                for (int fn = 0; fn < 10; ++fn) {
#pragma unroll
                    for (int cb = 0; cb < 2; ++cb) {
                        float v = acc[mf][fn][h * 2 + cb];
                        v = fmaxf(v, __shfl_xor_sync(0xFFFFFFFFu, v, 4));
                        v = fmaxf(v, __shfl_xor_sync(0xFFFFFFFFu, v, 8));
                        if (((lid >> 2) & 3) == 0) {
                            int group = mf * 4 + h * 2 + (lid >> 4);
                            int img = bx * 24 + wm * 12 + group;
                            int col = fn * 8 + c0b + cb;
                            if (col < NR)
                                g_colmax_part[(((size_t)mt * BATCH + cdx) * BATCH + img) * NPAD + col] = v;
                        }
                    }
                }
            }
        }
    }
}

// ===== combine partial tiles into logit matrices =====
__global__ void fg_combine_kernel()
{
    const int c = blockIdx.x;    // 96
    const int b = threadIdx.x;   // 96
    float rs = 0.f;
#pragma unroll
    for (int t = 0; t < NTILES; ++t)
        rs += g_rowsum_part[((size_t)t * BATCH + b) * BATCH + c];
    g_i2t[b * BATCH + c] = rs * (1.0f / NQ);

    const float* p0 = &g_colmax_part[(((size_t)0 * BATCH + c) * BATCH + b) * NPAD];
    const float* p1 = &g_colmax_part[(((size_t)1 * BATCH + c) * BATCH + b) * NPAD];
    const float* p2 = &g_colmax_part[(((size_t)2 * BATCH + c) * BATCH + b) * NPAD];
    float s = 0.f;
#pragma unroll
    for (int rr = 0; rr < NR; ++rr) s += fmaxf(fmaxf(p0[rr], p1[rr]), p2[rr]);
    g_t2i[c * BATCH + b] = s * (1.0f / NR);
}

// ===== per-row cross-entropy (one warp per row, 192 rows) =====
__global__ void fg_rowce_kernel()
{
    const int wid = threadIdx.x >> 5;
    const int lid = threadIdx.x & 31;
    const int row = blockIdx.x * 32 + wid;
    if (row >= 2 * BATCH) return;
    const int label = (row < BATCH) ? row : row - BATCH;
    const float* base = (row < BATCH) ? &g_i2t[row * BATCH] : &g_t2i[(row - BATCH) * BATCH];

    float v0 = base[lid], v1 = base[lid + 32], v2 = base[lid + 64];
    float m = fmaxf(v0, fmaxf(v1, v2));
#pragma unroll
    for (int off = 16; off > 0; off >>= 1)
        m = fmaxf(m, __shfl_xor_sync(0xFFFFFFFFu, m, off));
    float s = expf(v0 - m) + expf(v1 - m) + expf(v2 - m);
#pragma unroll
    for (int off = 16; off > 0; off >>= 1)
        s += __shfl_xor_sync(0xFFFFFFFFu, s, off);
    float lse = m + logf(s);
    int slot = label >> 5, src = label & 31;
    float mine = (slot == 0) ? v0 : ((slot == 1) ? v1 : v2);
    float dval = __shfl_sync(0xFFFFFFFFu, mine, src);
    if (lid == 0) g_contrib[row] = lse - dval;
}

__global__ void fg_final_kernel(float* __restrict__ out)
{
    __shared__ float sred[192];
    const int t = threadIdx.x;
    sred[t] = g_contrib[t];
    __syncthreads();
    if (t == 0) {
        float s = 0.f;
        for (int i = 0; i < 2 * BATCH; i++) s += sred[i];
        out[0] = s * (0.5f / BATCH);
    }
}

extern "C" void kernel_launch(void* const* d_in, const int* in_sizes, int n_in,
                              void* d_out, int out_size)
{
    const float* img;
    const float* txt;
    if (in_sizes[0] > in_sizes[1]) { img = (const float*)d_in[0]; txt = (const float*)d_in[1]; }
    else                           { img = (const float*)d_in[1]; txt = (const float*)d_in[0]; }
    float* out = (float*)d_out;

    constexpr int STAGE = 2 * (96 * ROWB) + 2 * (2 * NPAD * ROWB);   // 40960
    constexpr int SMEM  = 2 * STAGE + 1024;   // 82944 -> 2 CTAs/SM

    static int configured = 0;
    if (!configured) {
        cudaFuncSetAttribute(fg_mma_kernel<false>, cudaFuncAttributeMaxDynamicSharedMemorySize, SMEM);
        cudaFuncSetAttribute(fg_mma_kernel<true>,  cudaFuncAttributeMaxDynamicSharedMemorySize, SMEM);
        configured = 1;
    }

    // bf16 hi/lo split of both inputs
    {
        __nv_bfloat16 *ib0, *ib1, *tb0, *tb1;
        cudaGetSymbolAddress((void**)&ib0, g_ib0);
        cudaGetSymbolAddress((void**)&ib1, g_ib1);
        cudaGetSymbolAddress((void**)&tb0, g_tb0);
        cudaGetSymbolAddress((void**)&tb1, g_tb1);
        int ni = BATCH * NQ * DIM, nt = BATCH * NR * DIM;
        fg_split_kernel<<<(ni + 255) / 256, 256>>>(img, ib0, ib1, ni);
        fg_split_kernel<<<(nt + 255) / 256, 256>>>(txt, tb0, tb1, nt);
    }

    // m-tiles 0,1: rows 0-95, 96-191 (all valid).
    fg_mma_kernel<false><<<dim3(BATCH, BATCH / 2, 2), 128, SMEM>>>(0);
    // tail: rows 192-195 of all images, compacted 4 rows/image x 24 images/tile.
    fg_mma_kernel<true><<<dim3(4, BATCH / 2, 1), 128, SMEM>>>(2);
    fg_combine_kernel<<<BATCH, BATCH>>>();
    fg_rowce_kernel<<<6, 1024>>>();
    fg_final_kernel<<<1, 192>>>(out);
}